// round 1
// baseline (speedup 1.0000x reference)
#include <cuda_runtime.h>
#include <cstdint>

#define NMAX   20000
#define EMAX   160000
#define D      512
#define NBUK   11
#define TM     128
#define MAXT   ((NMAX + TM - 1) / TM + NBUK)   // 168
#define BN_EPS 1e-5f

// ---------------- scratch (device globals; no allocation allowed) -------------
__device__ int   g_deg[NMAX];
__device__ int   g_off[NMAX + 1];
__device__ int   g_cur[NMAX];
__device__ int   g_csr[EMAX];
__device__ int   g_bcnt[NBUK];
__device__ int   g_boff[NBUK + 1];
__device__ int   g_bcur[NBUK];
__device__ int   g_perm[NMAX];
__device__ int   g_tile_bucket[MAXT];
__device__ int   g_tile_row[MAXT];
__device__ int   g_tile_rows[MAXT];
__device__ int   g_ntiles;
__device__ float g_h[(size_t)NMAX * D];     // neighbor sums
__device__ float g_x[(size_t)NMAX * D];     // pre-BN linear output
__device__ float g_sum[D], g_sumsq[D], g_scale[D], g_shift[D];

// ---------------- small helpers ----------------------------------------------
__device__ __forceinline__ uint32_t f2tf32(float f) {
    uint32_t u;
    asm("cvt.rna.tf32.f32 %0, %1;" : "=r"(u) : "f"(f));
    return u;
}

__device__ __forceinline__ void mma_tf32(float c[4], const uint32_t a[4],
                                         const uint32_t b[2]) {
    asm volatile(
        "mma.sync.aligned.m16n8k8.row.col.f32.tf32.tf32.f32 "
        "{%0,%1,%2,%3}, {%4,%5,%6,%7}, {%8,%9}, {%0,%1,%2,%3};\n"
        : "+f"(c[0]), "+f"(c[1]), "+f"(c[2]), "+f"(c[3])
        : "r"(a[0]), "r"(a[1]), "r"(a[2]), "r"(a[3]), "r"(b[0]), "r"(b[1]));
}

// ---------------- setup kernels ----------------------------------------------
__global__ void k_zero(int n) {
    int i = blockIdx.x * blockDim.x + threadIdx.x;
    if (i < n) g_deg[i] = 0;
    if (i < D) { g_sum[i] = 0.f; g_sumsq[i] = 0.f; }
    if (i < NBUK) { g_bcnt[i] = 0; g_bcur[i] = 0; }
}

__global__ void k_degcount(const int* __restrict__ dst, int e) {
    int i = blockIdx.x * blockDim.x + threadIdx.x;
    if (i < e) atomicAdd(&g_deg[dst[i]], 1);
}

// exclusive scan of degrees -> CSR offsets + cursors + degree-bucket histogram
__global__ void k_scan(int n) {
    __shared__ int sdata[1024];
    __shared__ int bc[NBUK];
    int t = threadIdx.x;
    int carry = 0;
    int nchunk = (n + 1023) >> 10;
    for (int ch = 0; ch < nchunk; ch++) {
        int i = ch * 1024 + t;
        int v = (i < n) ? g_deg[i] : 0;
        sdata[t] = v;
        __syncthreads();
        for (int s = 1; s < 1024; s <<= 1) {
            int x = (t >= s) ? sdata[t - s] : 0;
            __syncthreads();
            sdata[t] += x;
            __syncthreads();
        }
        if (i < n) {
            int ex = carry + sdata[t] - v;
            g_off[i] = ex;
            g_cur[i] = ex;
        }
        carry += sdata[1023];
        __syncthreads();
    }
    if (t == 0) g_off[n] = carry;
    if (t < NBUK) bc[t] = 0;
    __syncthreads();
    for (int i = t; i < n; i += 1024) {
        int dd = g_deg[i];
        if (dd > NBUK - 1) dd = NBUK - 1;
        atomicAdd(&bc[dd], 1);
    }
    __syncthreads();
    if (t == 0) {
        int acc = 0;
        for (int dd = 0; dd < NBUK; dd++) {
            g_bcnt[dd] = bc[dd];
            g_boff[dd] = acc;
            acc += bc[dd];
        }
        g_boff[NBUK] = acc;
    }
}

__global__ void k_csrfill(const int* __restrict__ src, const int* __restrict__ dst,
                          int e) {
    int i = blockIdx.x * blockDim.x + threadIdx.x;
    if (i < e) {
        int pos = atomicAdd(&g_cur[dst[i]], 1);
        g_csr[pos] = src[i];
    }
}

__global__ void k_bucketfill(int n) {
    int v = blockIdx.x * blockDim.x + threadIdx.x;
    if (v < n) {
        int dd = g_deg[v];
        if (dd > NBUK - 1) dd = NBUK - 1;
        int pos = g_boff[dd] + atomicAdd(&g_bcur[dd], 1);
        g_perm[pos] = v;
    }
}

__global__ void k_tilemap() {
    if (threadIdx.x == 0 && blockIdx.x == 0) {
        int t = 0;
        for (int dd = 0; dd < NBUK; dd++) {
            int c = g_bcnt[dd], o = g_boff[dd];
            for (int r = 0; r < c; r += TM) {
                g_tile_bucket[t] = dd;
                g_tile_row[t]    = o + r;
                g_tile_rows[t]   = (c - r < TM) ? (c - r) : TM;
                t++;
            }
        }
        g_ntiles = t;
    }
}

// ---------------- neighbor sum ------------------------------------------------
__global__ void k_nbrsum(const float* __restrict__ feats) {
    int v = blockIdx.x;
    int t = threadIdx.x;             // 128 threads -> one float4 each
    float4 acc = make_float4(0.f, 0.f, 0.f, 0.f);
    int beg = g_off[v], end = g_off[v + 1];
    for (int j = beg; j < end; j++) {
        int u = g_csr[j];
        float4 w = *reinterpret_cast<const float4*>(feats + (size_t)u * D + t * 4);
        acc.x += w.x; acc.y += w.y; acc.z += w.z; acc.w += w.w;
    }
    *reinterpret_cast<float4*>(g_h + (size_t)v * D + t * 4) = acc;
}

// ---------------- bucketed tf32 GEMM -------------------------------------------
// x[node] = [h[node] | feats[node]] (K=1024) @ [Wl[d] ; Wr[d]] (1024x512) + bl[d]
#define TN  128
#define TK  32
#define APITCH (TK + 4)     // bank-conflict-free for A frags
#define BPITCH (TN + 8)     // bank-conflict-free for B frags

__global__ __launch_bounds__(256, 1)
void k_gemm(const float* __restrict__ feats, const float* __restrict__ Wl,
            const float* __restrict__ Wr, const float* __restrict__ bl) {
    int tileId = blockIdx.y;
    if (tileId >= g_ntiles) return;
    int d     = g_tile_bucket[tileId];
    int row0  = g_tile_row[tileId];
    int nrows = g_tile_rows[tileId];
    int n0    = blockIdx.x * TN;

    __shared__ uint32_t As[TM][APITCH];
    __shared__ uint32_t Bs[TK][BPITCH];
    __shared__ int perm_s[TM];

    int tid  = threadIdx.x;
    int lane = tid & 31;
    int warp = tid >> 5;
    int grp  = lane >> 2;
    int tig  = lane & 3;
    int wrow0 = (warp & 1) * 64;     // 2 warp-rows of 64
    int wcol0 = (warp >> 1) * 32;    // 4 warp-cols of 32

    if (tid < TM) perm_s[tid] = (tid < nrows) ? g_perm[row0 + tid] : -1;
    __syncthreads();

    float acc[4][4][4];
#pragma unroll
    for (int mi = 0; mi < 4; mi++)
#pragma unroll
        for (int ni = 0; ni < 4; ni++)
#pragma unroll
            for (int q = 0; q < 4; q++) acc[mi][ni][q] = 0.f;

    float4 aR[4], bR[4];

    auto load_stage = [&](int kk) {
        const float* aptr = (kk < 512) ? g_h : feats;
        int kb = kk & 511;
#pragma unroll
        for (int p = 0; p < 4; p++) {
            int s = tid + p * 256;
            int row = s >> 3, f4 = s & 7;
            int node = perm_s[row];
            if (node >= 0)
                aR[p] = *reinterpret_cast<const float4*>(
                    aptr + (size_t)node * D + kb + f4 * 4);
            else
                aR[p] = make_float4(0.f, 0.f, 0.f, 0.f);
        }
        const float* wptr = (kk < 512) ? Wl : Wr;
#pragma unroll
        for (int p = 0; p < 4; p++) {
            int s = tid + p * 256;
            int kr = s >> 5, nf4 = s & 31;
            bR[p] = *reinterpret_cast<const float4*>(
                wptr + ((size_t)d * D + kb + kr) * D + n0 + nf4 * 4);
        }
    };
    auto store_stage = [&]() {
#pragma unroll
        for (int p = 0; p < 4; p++) {
            int s = tid + p * 256;
            int row = s >> 3, f4 = s & 7;
            uint32_t* q = &As[row][f4 * 4];
            q[0] = f2tf32(aR[p].x); q[1] = f2tf32(aR[p].y);
            q[2] = f2tf32(aR[p].z); q[3] = f2tf32(aR[p].w);
        }
#pragma unroll
        for (int p = 0; p < 4; p++) {
            int s = tid + p * 256;
            int kr = s >> 5, nf4 = s & 31;
            uint32_t* q = &Bs[kr][nf4 * 4];
            q[0] = f2tf32(bR[p].x); q[1] = f2tf32(bR[p].y);
            q[2] = f2tf32(bR[p].z); q[3] = f2tf32(bR[p].w);
        }
    };

    load_stage(0);
    store_stage();
    __syncthreads();

#pragma unroll 1
    for (int kk = 0; kk < 1024; kk += TK) {
        bool has_next = (kk + TK) < 1024;
        if (has_next) load_stage(kk + TK);
#pragma unroll
        for (int k8 = 0; k8 < TK; k8 += 8) {
            uint32_t af[4][4], bf[4][2];
#pragma unroll
            for (int mi = 0; mi < 4; mi++) {
                int r0 = wrow0 + mi * 16 + grp;
                af[mi][0] = As[r0][k8 + tig];
                af[mi][1] = As[r0 + 8][k8 + tig];
                af[mi][2] = As[r0][k8 + tig + 4];
                af[mi][3] = As[r0 + 8][k8 + tig + 4];
            }
#pragma unroll
            for (int ni = 0; ni < 4; ni++) {
                int c0 = wcol0 + ni * 8 + grp;
                bf[ni][0] = Bs[k8 + tig][c0];
                bf[ni][1] = Bs[k8 + tig + 4][c0];
            }
#pragma unroll
            for (int mi = 0; mi < 4; mi++)
#pragma unroll
                for (int ni = 0; ni < 4; ni++)
                    mma_tf32(acc[mi][ni], af[mi], bf[ni]);
        }
        __syncthreads();
        if (has_next) {
            store_stage();
            __syncthreads();
        }
    }

    // epilogue: add bias, scatter to g_x
#pragma unroll
    for (int mi = 0; mi < 4; mi++) {
        int r0 = wrow0 + mi * 16 + grp;
        int node0 = perm_s[r0];
        int node1 = perm_s[r0 + 8];
#pragma unroll
        for (int ni = 0; ni < 4; ni++) {
            int cc = wcol0 + ni * 8 + 2 * tig;
            float2 bias = *reinterpret_cast<const float2*>(
                bl + (size_t)d * D + n0 + cc);
            if (node0 >= 0) {
                float2 v;
                v.x = acc[mi][ni][0] + bias.x;
                v.y = acc[mi][ni][1] + bias.y;
                *reinterpret_cast<float2*>(g_x + (size_t)node0 * D + n0 + cc) = v;
            }
            if (node1 >= 0) {
                float2 v;
                v.x = acc[mi][ni][2] + bias.x;
                v.y = acc[mi][ni][3] + bias.y;
                *reinterpret_cast<float2*>(g_x + (size_t)node1 * D + n0 + cc) = v;
            }
        }
    }
}

// ---------------- BN stats ------------------------------------------------------
__global__ void k_stats(int n, int rpg) {
    int tid = threadIdx.x;
    int c = blockIdx.x * 128 + (tid & 127);
    int half = tid >> 7;
    int r0 = blockIdx.y * rpg;
    int r1 = r0 + rpg; if (r1 > n) r1 = n;
    float s = 0.f, q = 0.f;
    for (int r = r0 + half; r < r1; r += 2) {
        float v = g_x[(size_t)r * D + c];
        s += v; q += v * v;
    }
    __shared__ float ss[256], qq[256];
    ss[tid] = s; qq[tid] = q;
    __syncthreads();
    if (half == 0) {
        s = ss[tid] + ss[tid + 128];
        q = qq[tid] + qq[tid + 128];
        atomicAdd(&g_sum[c], s);
        atomicAdd(&g_sumsq[c], q);
    }
}

__global__ void k_finalize(int n, const float* __restrict__ gamma,
                           const float* __restrict__ beta) {
    int c = threadIdx.x;
    float invn = 1.f / (float)n;
    float mean = g_sum[c] * invn;
    float var  = g_sumsq[c] * invn - mean * mean;
    float s    = gamma[c] * rsqrtf(var + BN_EPS);
    g_scale[c] = s;
    g_shift[c] = beta[c] - mean * s;
}

// ---------------- max aggregation (BN affine fused, sign-safe) -----------------
__global__ void k_maxagg(float* __restrict__ out) {
    int v = blockIdx.x;
    int t = threadIdx.x;
    float4 mx = *reinterpret_cast<const float4*>(g_x + (size_t)v * D + t * 4);
    float4 mn = mx;
    int beg = g_off[v], end = g_off[v + 1];
    for (int j = beg; j < end; j++) {
        int u = g_csr[j];
        float4 w = *reinterpret_cast<const float4*>(g_x + (size_t)u * D + t * 4);
        mx.x = fmaxf(mx.x, w.x); mn.x = fminf(mn.x, w.x);
        mx.y = fmaxf(mx.y, w.y); mn.y = fminf(mn.y, w.y);
        mx.z = fmaxf(mx.z, w.z); mn.z = fminf(mn.z, w.z);
        mx.w = fmaxf(mx.w, w.w); mn.w = fminf(mn.w, w.w);
    }
    float4 sc = reinterpret_cast<const float4*>(g_scale)[t];
    float4 sh = reinterpret_cast<const float4*>(g_shift)[t];
    float4 r;
    r.x = (sc.x >= 0.f ? mx.x : mn.x) * sc.x + sh.x;
    r.y = (sc.y >= 0.f ? mx.y : mn.y) * sc.y + sh.y;
    r.z = (sc.z >= 0.f ? mx.z : mn.z) * sc.z + sh.z;
    r.w = (sc.w >= 0.f ? mx.w : mn.w) * sc.w + sh.w;
    reinterpret_cast<float4*>(out + (size_t)v * D)[t] = r;
}

// ---------------- launch --------------------------------------------------------
extern "C" void kernel_launch(void* const* d_in, const int* in_sizes, int n_in,
                              void* d_out, int out_size) {
    const float* feats = (const float*)d_in[0];
    const int*   src   = (const int*)d_in[1];
    const int*   dst   = (const int*)d_in[2];
    const float* Wl    = (const float*)d_in[3];
    const float* Wr    = (const float*)d_in[4];
    const float* bl    = (const float*)d_in[5];
    const float* gamma = (const float*)d_in[6];
    const float* beta  = (const float*)d_in[7];
    float* out = (float*)d_out;

    int n = in_sizes[0] / D;
    int e = in_sizes[1];

    k_zero<<<(n + 255) / 256, 256>>>(n);
    k_degcount<<<(e + 255) / 256, 256>>>(dst, e);
    k_scan<<<1, 1024>>>(n);
    k_csrfill<<<(e + 255) / 256, 256>>>(src, dst, e);
    k_bucketfill<<<(n + 255) / 256, 256>>>(n);
    k_tilemap<<<1, 32>>>();
    k_nbrsum<<<n, 128>>>(feats);
    k_gemm<<<dim3(D / TN, MAXT), 256>>>(feats, Wl, Wr, bl);
    int rpg = (n + 39) / 40;
    k_stats<<<dim3(4, 40), 256>>>(n, rpg);
    k_finalize<<<1, D>>>(n, gamma, beta);
    k_maxagg<<<n, 128>>>(out);
}

// round 2
// speedup vs baseline: 1.0049x; 1.0049x over previous
#include <cuda_runtime.h>
#include <cstdint>

#define NMAX   20000
#define EMAX   160000
#define D      512
#define NBUK   11
#define TM     128
#define MAXT   ((NMAX + TM - 1) / TM + NBUK)   // 168
#define BN_EPS 1e-5f

// ---------------- scratch (device globals; no allocation allowed) -------------
__device__ int   g_deg[NMAX];
__device__ int   g_off[NMAX + 1];
__device__ int   g_cur[NMAX];
__device__ int   g_csr[EMAX];
__device__ int   g_bcnt[NBUK];
__device__ int   g_boff[NBUK + 1];
__device__ int   g_bcur[NBUK];
__device__ int   g_perm[NMAX];
__device__ int   g_tile_bucket[MAXT];
__device__ int   g_tile_row[MAXT];
__device__ int   g_tile_rows[MAXT];
__device__ int   g_ntiles;
__device__ float g_h[(size_t)NMAX * D];     // neighbor sums
__device__ float g_x[(size_t)NMAX * D];     // pre-BN linear output
__device__ float g_sum[D], g_sumsq[D], g_scale[D], g_shift[D];

// ---------------- small helpers ----------------------------------------------
__device__ __forceinline__ uint32_t f2tf32(float f) {
    uint32_t u;
    asm("cvt.rna.tf32.f32 %0, %1;" : "=r"(u) : "f"(f));
    return u;
}

__device__ __forceinline__ void mma_tf32(float c[4], const uint32_t a[4],
                                         const uint32_t b[2]) {
    asm volatile(
        "mma.sync.aligned.m16n8k8.row.col.f32.tf32.tf32.f32 "
        "{%0,%1,%2,%3}, {%4,%5,%6,%7}, {%8,%9}, {%0,%1,%2,%3};\n"
        : "+f"(c[0]), "+f"(c[1]), "+f"(c[2]), "+f"(c[3])
        : "r"(a[0]), "r"(a[1]), "r"(a[2]), "r"(a[3]), "r"(b[0]), "r"(b[1]));
}

// ---------------- setup kernels ----------------------------------------------
__global__ void k_zero(int n) {
    int i = blockIdx.x * blockDim.x + threadIdx.x;
    if (i < n) g_deg[i] = 0;
    if (i < D) { g_sum[i] = 0.f; g_sumsq[i] = 0.f; }
    if (i < NBUK) { g_bcnt[i] = 0; g_bcur[i] = 0; }
}

__global__ void k_degcount(const int* __restrict__ dst, int e) {
    int i = blockIdx.x * blockDim.x + threadIdx.x;
    if (i < e) atomicAdd(&g_deg[dst[i]], 1);
}

// exclusive scan of degrees -> CSR offsets + cursors + degree-bucket histogram
__global__ void k_scan(int n) {
    __shared__ int sdata[1024];
    __shared__ int bc[NBUK];
    int t = threadIdx.x;
    int carry = 0;
    int nchunk = (n + 1023) >> 10;
    for (int ch = 0; ch < nchunk; ch++) {
        int i = ch * 1024 + t;
        int v = (i < n) ? g_deg[i] : 0;
        sdata[t] = v;
        __syncthreads();
        for (int s = 1; s < 1024; s <<= 1) {
            int x = (t >= s) ? sdata[t - s] : 0;
            __syncthreads();
            sdata[t] += x;
            __syncthreads();
        }
        if (i < n) {
            int ex = carry + sdata[t] - v;
            g_off[i] = ex;
            g_cur[i] = ex;
        }
        carry += sdata[1023];
        __syncthreads();
    }
    if (t == 0) g_off[n] = carry;
    if (t < NBUK) bc[t] = 0;
    __syncthreads();
    for (int i = t; i < n; i += 1024) {
        int dd = g_deg[i];
        if (dd > NBUK - 1) dd = NBUK - 1;
        atomicAdd(&bc[dd], 1);
    }
    __syncthreads();
    if (t == 0) {
        int acc = 0;
        for (int dd = 0; dd < NBUK; dd++) {
            g_bcnt[dd] = bc[dd];
            g_boff[dd] = acc;
            acc += bc[dd];
        }
        g_boff[NBUK] = acc;
    }
}

__global__ void k_csrfill(const int* __restrict__ src, const int* __restrict__ dst,
                          int e) {
    int i = blockIdx.x * blockDim.x + threadIdx.x;
    if (i < e) {
        int pos = atomicAdd(&g_cur[dst[i]], 1);
        g_csr[pos] = src[i];
    }
}

__global__ void k_bucketfill(int n) {
    int v = blockIdx.x * blockDim.x + threadIdx.x;
    if (v < n) {
        int dd = g_deg[v];
        if (dd > NBUK - 1) dd = NBUK - 1;
        int pos = g_boff[dd] + atomicAdd(&g_bcur[dd], 1);
        g_perm[pos] = v;
    }
}

__global__ void k_tilemap() {
    if (threadIdx.x == 0 && blockIdx.x == 0) {
        int t = 0;
        for (int dd = 0; dd < NBUK; dd++) {
            int c = g_bcnt[dd], o = g_boff[dd];
            for (int r = 0; r < c; r += TM) {
                g_tile_bucket[t] = dd;
                g_tile_row[t]    = o + r;
                g_tile_rows[t]   = (c - r < TM) ? (c - r) : TM;
                t++;
            }
        }
        g_ntiles = t;
    }
}

// ---------------- neighbor sum ------------------------------------------------
__global__ void k_nbrsum(const float* __restrict__ feats) {
    int v = blockIdx.x;
    int t = threadIdx.x;             // 128 threads -> one float4 each
    float4 acc = make_float4(0.f, 0.f, 0.f, 0.f);
    int beg = g_off[v], end = g_off[v + 1];
    for (int j = beg; j < end; j++) {
        int u = g_csr[j];
        float4 w = *reinterpret_cast<const float4*>(feats + (size_t)u * D + t * 4);
        acc.x += w.x; acc.y += w.y; acc.z += w.z; acc.w += w.w;
    }
    *reinterpret_cast<float4*>(g_h + (size_t)v * D + t * 4) = acc;
}

// ---------------- bucketed tf32 GEMM -------------------------------------------
// x[node] = [h[node] | feats[node]] (K=1024) @ [Wl[d] ; Wr[d]] (1024x512) + bl[d]
#define TN  128
#define TK  32
#define APITCH (TK + 4)     // bank-conflict-free for A frags
#define BPITCH (TN + 8)     // bank-conflict-free for B frags

__global__ __launch_bounds__(256, 1)
void k_gemm(const float* __restrict__ feats, const float* __restrict__ Wl,
            const float* __restrict__ Wr, const float* __restrict__ bl) {
    int tileId = blockIdx.y;
    if (tileId >= g_ntiles) return;
    int d     = g_tile_bucket[tileId];
    int row0  = g_tile_row[tileId];
    int nrows = g_tile_rows[tileId];
    int n0    = blockIdx.x * TN;

    __shared__ uint32_t As[TM][APITCH];
    __shared__ uint32_t Bs[TK][BPITCH];
    __shared__ int perm_s[TM];

    int tid  = threadIdx.x;
    int lane = tid & 31;
    int warp = tid >> 5;
    int grp  = lane >> 2;
    int tig  = lane & 3;
    int wrow0 = (warp & 1) * 64;     // 2 warp-rows of 64
    int wcol0 = (warp >> 1) * 32;    // 4 warp-cols of 32

    if (tid < TM) perm_s[tid] = (tid < nrows) ? g_perm[row0 + tid] : -1;
    __syncthreads();

    float acc[4][4][4];
#pragma unroll
    for (int mi = 0; mi < 4; mi++)
#pragma unroll
        for (int ni = 0; ni < 4; ni++)
#pragma unroll
            for (int q = 0; q < 4; q++) acc[mi][ni][q] = 0.f;

    float4 aR[4], bR[4];

    auto load_stage = [&](int kk) {
        const float* aptr = (kk < 512) ? g_h : feats;
        int kb = kk & 511;
#pragma unroll
        for (int p = 0; p < 4; p++) {
            int s = tid + p * 256;
            int row = s >> 3, f4 = s & 7;
            int node = perm_s[row];
            if (node >= 0)
                aR[p] = *reinterpret_cast<const float4*>(
                    aptr + (size_t)node * D + kb + f4 * 4);
            else
                aR[p] = make_float4(0.f, 0.f, 0.f, 0.f);
        }
        const float* wptr = (kk < 512) ? Wl : Wr;
#pragma unroll
        for (int p = 0; p < 4; p++) {
            int s = tid + p * 256;
            int kr = s >> 5, nf4 = s & 31;
            bR[p] = *reinterpret_cast<const float4*>(
                wptr + ((size_t)d * D + kb + kr) * D + n0 + nf4 * 4);
        }
    };
    auto store_stage = [&]() {
#pragma unroll
        for (int p = 0; p < 4; p++) {
            int s = tid + p * 256;
            int row = s >> 3, f4 = s & 7;
            uint32_t* q = &As[row][f4 * 4];
            q[0] = f2tf32(aR[p].x); q[1] = f2tf32(aR[p].y);
            q[2] = f2tf32(aR[p].z); q[3] = f2tf32(aR[p].w);
        }
#pragma unroll
        for (int p = 0; p < 4; p++) {
            int s = tid + p * 256;
            int kr = s >> 5, nf4 = s & 31;
            uint32_t* q = &Bs[kr][nf4 * 4];
            q[0] = f2tf32(bR[p].x); q[1] = f2tf32(bR[p].y);
            q[2] = f2tf32(bR[p].z); q[3] = f2tf32(bR[p].w);
        }
    };

    load_stage(0);
    store_stage();
    __syncthreads();

#pragma unroll 1
    for (int kk = 0; kk < 1024; kk += TK) {
        bool has_next = (kk + TK) < 1024;
        if (has_next) load_stage(kk + TK);
#pragma unroll
        for (int k8 = 0; k8 < TK; k8 += 8) {
            uint32_t af[4][4], bf[4][2];
#pragma unroll
            for (int mi = 0; mi < 4; mi++) {
                int r0 = wrow0 + mi * 16 + grp;
                af[mi][0] = As[r0][k8 + tig];
                af[mi][1] = As[r0 + 8][k8 + tig];
                af[mi][2] = As[r0][k8 + tig + 4];
                af[mi][3] = As[r0 + 8][k8 + tig + 4];
            }
#pragma unroll
            for (int ni = 0; ni < 4; ni++) {
                int c0 = wcol0 + ni * 8 + grp;
                bf[ni][0] = Bs[k8 + tig][c0];
                bf[ni][1] = Bs[k8 + tig + 4][c0];
            }
#pragma unroll
            for (int mi = 0; mi < 4; mi++)
#pragma unroll
                for (int ni = 0; ni < 4; ni++)
                    mma_tf32(acc[mi][ni], af[mi], bf[ni]);
        }
        __syncthreads();
        if (has_next) {
            store_stage();
            __syncthreads();
        }
    }

    // epilogue: add bias, scatter to g_x
#pragma unroll
    for (int mi = 0; mi < 4; mi++) {
        int r0 = wrow0 + mi * 16 + grp;
        int node0 = perm_s[r0];
        int node1 = perm_s[r0 + 8];
#pragma unroll
        for (int ni = 0; ni < 4; ni++) {
            int cc = wcol0 + ni * 8 + 2 * tig;
            float2 bias = *reinterpret_cast<const float2*>(
                bl + (size_t)d * D + n0 + cc);
            if (node0 >= 0) {
                float2 v;
                v.x = acc[mi][ni][0] + bias.x;
                v.y = acc[mi][ni][1] + bias.y;
                *reinterpret_cast<float2*>(g_x + (size_t)node0 * D + n0 + cc) = v;
            }
            if (node1 >= 0) {
                float2 v;
                v.x = acc[mi][ni][2] + bias.x;
                v.y = acc[mi][ni][3] + bias.y;
                *reinterpret_cast<float2*>(g_x + (size_t)node1 * D + n0 + cc) = v;
            }
        }
    }
}

// ---------------- BN stats ------------------------------------------------------
__global__ void k_stats(int n, int rpg) {
    int tid = threadIdx.x;
    int c = blockIdx.x * 128 + (tid & 127);
    int half = tid >> 7;
    int r0 = blockIdx.y * rpg;
    int r1 = r0 + rpg; if (r1 > n) r1 = n;
    float s = 0.f, q = 0.f;
    for (int r = r0 + half; r < r1; r += 2) {
        float v = g_x[(size_t)r * D + c];
        s += v; q += v * v;
    }
    __shared__ float ss[256], qq[256];
    ss[tid] = s; qq[tid] = q;
    __syncthreads();
    if (half == 0) {
        s = ss[tid] + ss[tid + 128];
        q = qq[tid] + qq[tid + 128];
        atomicAdd(&g_sum[c], s);
        atomicAdd(&g_sumsq[c], q);
    }
}

__global__ void k_finalize(int n, const float* __restrict__ gamma,
                           const float* __restrict__ beta) {
    int c = threadIdx.x;
    float invn = 1.f / (float)n;
    float mean = g_sum[c] * invn;
    float var  = g_sumsq[c] * invn - mean * mean;
    float s    = gamma[c] * rsqrtf(var + BN_EPS);
    g_scale[c] = s;
    g_shift[c] = beta[c] - mean * s;
}

// ---------------- max aggregation (BN affine fused, sign-safe) -----------------
__global__ void k_maxagg(float* __restrict__ out) {
    int v = blockIdx.x;
    int t = threadIdx.x;
    float4 mx = *reinterpret_cast<const float4*>(g_x + (size_t)v * D + t * 4);
    float4 mn = mx;
    int beg = g_off[v], end = g_off[v + 1];
    for (int j = beg; j < end; j++) {
        int u = g_csr[j];
        float4 w = *reinterpret_cast<const float4*>(g_x + (size_t)u * D + t * 4);
        mx.x = fmaxf(mx.x, w.x); mn.x = fminf(mn.x, w.x);
        mx.y = fmaxf(mx.y, w.y); mn.y = fminf(mn.y, w.y);
        mx.z = fmaxf(mx.z, w.z); mn.z = fminf(mn.z, w.z);
        mx.w = fmaxf(mx.w, w.w); mn.w = fminf(mn.w, w.w);
    }
    float4 sc = reinterpret_cast<const float4*>(g_scale)[t];
    float4 sh = reinterpret_cast<const float4*>(g_shift)[t];
    float4 r;
    r.x = (sc.x >= 0.f ? mx.x : mn.x) * sc.x + sh.x;
    r.y = (sc.y >= 0.f ? mx.y : mn.y) * sc.y + sh.y;
    r.z = (sc.z >= 0.f ? mx.z : mn.z) * sc.z + sh.z;
    r.w = (sc.w >= 0.f ? mx.w : mn.w) * sc.w + sh.w;
    reinterpret_cast<float4*>(out + (size_t)v * D)[t] = r;
}

// ---------------- launch --------------------------------------------------------
extern "C" void kernel_launch(void* const* d_in, const int* in_sizes, int n_in,
                              void* d_out, int out_size) {
    const float* feats = (const float*)d_in[0];
    const int*   src   = (const int*)d_in[1];
    const int*   dst   = (const int*)d_in[2];
    const float* Wl    = (const float*)d_in[3];
    const float* Wr    = (const float*)d_in[4];
    const float* bl    = (const float*)d_in[5];
    const float* gamma = (const float*)d_in[6];
    const float* beta  = (const float*)d_in[7];
    float* out = (float*)d_out;

    int n = in_sizes[0] / D;
    int e = in_sizes[1];

    k_zero<<<(n + 255) / 256, 256>>>(n);
    k_degcount<<<(e + 255) / 256, 256>>>(dst, e);
    k_scan<<<1, 1024>>>(n);
    k_csrfill<<<(e + 255) / 256, 256>>>(src, dst, e);
    k_bucketfill<<<(n + 255) / 256, 256>>>(n);
    k_tilemap<<<1, 32>>>();
    k_nbrsum<<<n, 128>>>(feats);
    k_gemm<<<dim3(D / TN, MAXT), 256>>>(feats, Wl, Wr, bl);
    int rpg = (n + 39) / 40;
    k_stats<<<dim3(4, 40), 256>>>(n, rpg);
    k_finalize<<<1, D>>>(n, gamma, beta);
    k_maxagg<<<n, 128>>>(out);
}

// round 4
// speedup vs baseline: 1.2107x; 1.2048x over previous
#include <cuda_runtime.h>
#include <cstdint>

#define NMAX   20000
#define EMAX   160000
#define D      512
#define NBUK   11
#define TM     128
#define MAXT   ((NMAX + TM - 1) / TM + NBUK)   // 168
#define BN_EPS 1e-5f

#define TN  128
#define TK  32
#define APITCH 36    // words; 144B rows, 16B-aligned, conflict-free frag reads
#define BPITCH 136   // words; 544B rows, 16B-aligned, conflict-free frag reads
#define A_WORDS (TM * APITCH)            // 4608
#define B_WORDS (TK * BPITCH)            // 4352
#define SMEM_WORDS (2*A_WORDS + 2*B_WORDS)
#define SMEM_BYTES (SMEM_WORDS*4 + TM*4) // buffers + perm_s

// ---------------- scratch (device globals; no allocation allowed) -------------
__device__ int   g_deg[NMAX];
__device__ int   g_off[NMAX + 1];
__device__ int   g_cur[NMAX];
__device__ int   g_csr[EMAX];
__device__ int   g_bcnt[NBUK];
__device__ int   g_boff[NBUK + 1];
__device__ int   g_bcur[NBUK];
__device__ int   g_perm[NMAX];
__device__ int   g_tile_bucket[MAXT];
__device__ int   g_tile_row[MAXT];
__device__ int   g_tile_rows[MAXT];
__device__ int   g_ntiles;
__device__ float g_h[(size_t)NMAX * D];     // neighbor sums
__device__ float g_x[(size_t)NMAX * D];     // pre-BN linear output
__device__ float g_sum[D], g_sumsq[D], g_scale[D], g_shift[D];

// ---------------- helpers -----------------------------------------------------
__device__ __forceinline__ void mma_tf32(float c[4], const uint32_t a[4],
                                         const uint32_t b[2]) {
    asm volatile(
        "mma.sync.aligned.m16n8k8.row.col.f32.tf32.tf32.f32 "
        "{%0,%1,%2,%3}, {%4,%5,%6,%7}, {%8,%9}, {%0,%1,%2,%3};\n"
        : "+f"(c[0]), "+f"(c[1]), "+f"(c[2]), "+f"(c[3])
        : "r"(a[0]), "r"(a[1]), "r"(a[2]), "r"(a[3]), "r"(b[0]), "r"(b[1]));
}

__device__ __forceinline__ void cp_async16(uint32_t saddr, const void* gaddr,
                                           int src_bytes) {
    asm volatile("cp.async.cg.shared.global [%0], [%1], 16, %2;\n"
                 :: "r"(saddr), "l"(gaddr), "r"(src_bytes));
}
__device__ __forceinline__ void cp_commit() {
    asm volatile("cp.async.commit_group;\n");
}
__device__ __forceinline__ void cp_wait1() {
    asm volatile("cp.async.wait_group 1;\n");
}

// ---------------- setup kernels ------------------------------------------------
__global__ void k_zero(int n) {
    int i = blockIdx.x * blockDim.x + threadIdx.x;
    if (i < n) g_deg[i] = 0;
    if (i < D) { g_sum[i] = 0.f; g_sumsq[i] = 0.f; }
    if (i < NBUK) { g_bcnt[i] = 0; g_bcur[i] = 0; }
}

__global__ void k_degcount(const int* __restrict__ dst, int e) {
    int i = blockIdx.x * blockDim.x + threadIdx.x;
    if (i < e) atomicAdd(&g_deg[dst[i]], 1);
}

// scan (warp-shuffle based) + bucket histogram + tile map, one block
__global__ void k_scan(int n) {
    __shared__ int wsum[32];
    __shared__ int bc[NBUK];
    int t = threadIdx.x, lane = t & 31, w = t >> 5;
    if (t < NBUK) bc[t] = 0;
    int carry = 0;
    int nchunk = (n + 1023) >> 10;
    for (int ch = 0; ch < nchunk; ch++) {
        int i = ch * 1024 + t;
        int v = (i < n) ? g_deg[i] : 0;
        int x = v;
#pragma unroll
        for (int o = 1; o < 32; o <<= 1) {
            int y = __shfl_up_sync(0xffffffffu, x, o);
            if (lane >= o) x += y;
        }
        if (lane == 31) wsum[w] = x;
        __syncthreads();
        if (w == 0) {
            int s = wsum[lane];
#pragma unroll
            for (int o = 1; o < 32; o <<= 1) {
                int y = __shfl_up_sync(0xffffffffu, s, o);
                if (lane >= o) s += y;
            }
            wsum[lane] = s;
        }
        __syncthreads();
        int prev = (w > 0) ? wsum[w - 1] : 0;
        if (i < n) {
            int ex = carry + prev + x - v;
            g_off[i] = ex;
            g_cur[i] = ex;
        }
        carry += wsum[31];
        __syncthreads();
    }
    if (t == 0) g_off[n] = carry;
    for (int i = t; i < n; i += 1024) {
        int dd = g_deg[i];
        if (dd > NBUK - 1) dd = NBUK - 1;
        atomicAdd(&bc[dd], 1);
    }
    __syncthreads();
    if (t == 0) {
        int acc = 0;
        for (int dd = 0; dd < NBUK; dd++) {
            g_bcnt[dd] = bc[dd];
            g_boff[dd] = acc;
            acc += bc[dd];
        }
        g_boff[NBUK] = acc;
        int tt = 0;
        for (int dd = 0; dd < NBUK; dd++) {
            int c = bc[dd], o = g_boff[dd];
            for (int r = 0; r < c; r += TM) {
                g_tile_bucket[tt] = dd;
                g_tile_row[tt]    = o + r;
                g_tile_rows[tt]   = (c - r < TM) ? (c - r) : TM;
                tt++;
            }
        }
        g_ntiles = tt;
    }
}

// CSR fill + bucket fill (merged)
__global__ void k_fill(const int* __restrict__ src, const int* __restrict__ dst,
                       int e, int n) {
    int i = blockIdx.x * blockDim.x + threadIdx.x;
    if (i < e) {
        int pos = atomicAdd(&g_cur[dst[i]], 1);
        g_csr[pos] = src[i];
    }
    int v = i - e;
    if (v >= 0 && v < n) {
        int dd = g_deg[v];
        if (dd > NBUK - 1) dd = NBUK - 1;
        int pos = g_boff[dd] + atomicAdd(&g_bcur[dd], 1);
        g_perm[pos] = v;
    }
}

// ---------------- neighbor sum ---------------------------------------------------
__global__ void k_nbrsum(const float* __restrict__ feats) {
    int v = blockIdx.x;
    int t = threadIdx.x;
    float4 acc = make_float4(0.f, 0.f, 0.f, 0.f);
    int beg = g_off[v], end = g_off[v + 1];
    int j = beg;
    for (; j + 2 <= end; j += 2) {
        int u0 = g_csr[j], u1 = g_csr[j + 1];
        float4 w0 = *reinterpret_cast<const float4*>(feats + (size_t)u0 * D + t * 4);
        float4 w1 = *reinterpret_cast<const float4*>(feats + (size_t)u1 * D + t * 4);
        acc.x += w0.x + w1.x; acc.y += w0.y + w1.y;
        acc.z += w0.z + w1.z; acc.w += w0.w + w1.w;
    }
    if (j < end) {
        int u = g_csr[j];
        float4 w = *reinterpret_cast<const float4*>(feats + (size_t)u * D + t * 4);
        acc.x += w.x; acc.y += w.y; acc.z += w.z; acc.w += w.w;
    }
    *reinterpret_cast<float4*>(g_h + (size_t)v * D + t * 4) = acc;
}

// ---------------- bucketed tf32 GEMM, cp.async double-buffered -------------------
// x[node] = [h|feats](K=1024) @ [Wl[d];Wr[d]](1024x512) + bl[d]; BN stats fused.
__global__ __launch_bounds__(256, 1)
void k_gemm(const float* __restrict__ feats, const float* __restrict__ Wl,
            const float* __restrict__ Wr, const float* __restrict__ bl) {
    int tileId = blockIdx.y;
    if (tileId >= g_ntiles) return;
    int d     = g_tile_bucket[tileId];
    int row0  = g_tile_row[tileId];
    int nrows = g_tile_rows[tileId];
    int n0    = blockIdx.x * TN;

    extern __shared__ float smem[];
    float* Abuf0 = smem;
    float* Bbuf0 = smem + 2 * A_WORDS;
    int*   perm_s = (int*)(smem + SMEM_WORDS);

    int tid  = threadIdx.x;
    int lane = tid & 31;
    int warp = tid >> 5;
    int grp  = lane >> 2;
    int tig  = lane & 3;
    int wrow0 = (warp & 1) * 64;
    int wcol0 = (warp >> 1) * 32;

    if (tid < TM) perm_s[tid] = (tid < nrows) ? g_perm[row0 + tid] : -1;
    __syncthreads();

    // per-thread load coordinates
    int a_row = tid >> 3, a_f4 = tid & 7;     // + p*32 rows
    int b_kr  = tid >> 5, b_f4 = tid & 31;    // + p*8 k-rows

    uint32_t a_s[4], b_s[4];
    size_t a_goff[4];                          // ELEMENT offsets into g_h/feats
    int a_valid[4];
#pragma unroll
    for (int p = 0; p < 4; p++) {
        int row = a_row + p * 32;
        int node = perm_s[row];
        a_valid[p] = (node >= 0) ? 16 : 0;
        if (node < 0) node = 0;
        a_goff[p] = (size_t)node * D + (size_t)(a_f4 * 4);
        a_s[p] = (uint32_t)__cvta_generic_to_shared(&Abuf0[row * APITCH + a_f4 * 4]);
        b_s[p] = (uint32_t)__cvta_generic_to_shared(
            &Bbuf0[(b_kr + p * 8) * BPITCH + b_f4 * 4]);
    }
    const size_t wbase = (size_t)d * D * D + (size_t)n0;

    auto load_stage = [&](int kk, int buf) {
        const float* aptr = (kk < 512) ? g_h : feats;
        const float* wptr = (kk < 512) ? Wl : Wr;
        int kb = kk & 511;
        uint32_t boffA = buf ? (uint32_t)(A_WORDS * 4) : 0u;
#pragma unroll
        for (int p = 0; p < 4; p++)
            cp_async16(a_s[p] + boffA, aptr + a_goff[p] + kb, a_valid[p]);
        uint32_t boffB = buf ? (uint32_t)(B_WORDS * 4) : 0u;
#pragma unroll
        for (int p = 0; p < 4; p++)
            cp_async16(b_s[p] + boffB,
                       wptr + wbase + (size_t)(kb + b_kr + p * 8) * D + b_f4 * 4, 16);
    };

    float acc[4][4][4];
#pragma unroll
    for (int mi = 0; mi < 4; mi++)
#pragma unroll
        for (int ni = 0; ni < 4; ni++)
#pragma unroll
            for (int q = 0; q < 4; q++) acc[mi][ni][q] = 0.f;

    load_stage(0, 0);
    cp_commit();

    int buf = 0;
#pragma unroll 1
    for (int kt = 0; kt < 1024 / TK; kt++) {
        if (kt + 1 < 1024 / TK) load_stage((kt + 1) * TK, buf ^ 1);
        cp_commit();
        cp_wait1();
        __syncthreads();

        const uint32_t* As = (const uint32_t*)(Abuf0 + (buf ? A_WORDS : 0));
        const uint32_t* Bs = (const uint32_t*)(Bbuf0 + (buf ? B_WORDS : 0));
#pragma unroll
        for (int k8 = 0; k8 < TK; k8 += 8) {
            uint32_t af[4][4], bf[4][2];
#pragma unroll
            for (int mi = 0; mi < 4; mi++) {
                int r0 = wrow0 + mi * 16 + grp;
                af[mi][0] = As[r0 * APITCH + k8 + tig];
                af[mi][1] = As[(r0 + 8) * APITCH + k8 + tig];
                af[mi][2] = As[r0 * APITCH + k8 + tig + 4];
                af[mi][3] = As[(r0 + 8) * APITCH + k8 + tig + 4];
            }
#pragma unroll
            for (int ni = 0; ni < 4; ni++) {
                int c0 = wcol0 + ni * 8 + grp;
                bf[ni][0] = Bs[(k8 + tig) * BPITCH + c0];
                bf[ni][1] = Bs[(k8 + tig + 4) * BPITCH + c0];
            }
#pragma unroll
            for (int mi = 0; mi < 4; mi++)
#pragma unroll
                for (int ni = 0; ni < 4; ni++)
                    mma_tf32(acc[mi][ni], af[mi], bf[ni]);
        }
        __syncthreads();
        buf ^= 1;
    }

    // epilogue: bias add, store, fused BN column sums
    float2 bias[4];
#pragma unroll
    for (int ni = 0; ni < 4; ni++)
        bias[ni] = *reinterpret_cast<const float2*>(
            bl + (size_t)d * D + n0 + wcol0 + ni * 8 + 2 * tig);

    float s_sum[4][2] = {}, s_sq[4][2] = {};
#pragma unroll
    for (int mi = 0; mi < 4; mi++) {
        int r0 = wrow0 + mi * 16 + grp;
        int node0 = perm_s[r0];
        int node1 = perm_s[r0 + 8];
#pragma unroll
        for (int ni = 0; ni < 4; ni++) {
            int cc = wcol0 + ni * 8 + 2 * tig;
            float v0x = acc[mi][ni][0] + bias[ni].x;
            float v0y = acc[mi][ni][1] + bias[ni].y;
            float v1x = acc[mi][ni][2] + bias[ni].x;
            float v1y = acc[mi][ni][3] + bias[ni].y;
            if (node0 >= 0) {
                float2 v; v.x = v0x; v.y = v0y;
                *reinterpret_cast<float2*>(g_x + (size_t)node0 * D + n0 + cc) = v;
                s_sum[ni][0] += v0x; s_sq[ni][0] += v0x * v0x;
                s_sum[ni][1] += v0y; s_sq[ni][1] += v0y * v0y;
            }
            if (node1 >= 0) {
                float2 v; v.x = v1x; v.y = v1y;
                *reinterpret_cast<float2*>(g_x + (size_t)node1 * D + n0 + cc) = v;
                s_sum[ni][0] += v1x; s_sq[ni][0] += v1x * v1x;
                s_sum[ni][1] += v1y; s_sq[ni][1] += v1y * v1y;
            }
        }
    }
    // reduce across the 8 lane-groups (lanes differing in bits 2..4)
#pragma unroll
    for (int ni = 0; ni < 4; ni++)
#pragma unroll
        for (int b = 0; b < 2; b++) {
            float s = s_sum[ni][b], q = s_sq[ni][b];
#pragma unroll
            for (int off = 4; off < 32; off <<= 1) {
                s += __shfl_xor_sync(0xffffffffu, s, off);
                q += __shfl_xor_sync(0xffffffffu, q, off);
            }
            if (grp == 0) {
                int c = n0 + wcol0 + ni * 8 + 2 * tig + b;
                atomicAdd(&g_sum[c], s);
                atomicAdd(&g_sumsq[c], q);
            }
        }
}

// ---------------- BN finalize -----------------------------------------------------
__global__ void k_finalize(int n, const float* __restrict__ gamma,
                           const float* __restrict__ beta) {
    int c = threadIdx.x;
    float invn = 1.f / (float)n;
    float mean = g_sum[c] * invn;
    float var  = g_sumsq[c] * invn - mean * mean;
    float s    = gamma[c] * rsqrtf(var + BN_EPS);
    g_scale[c] = s;
    g_shift[c] = beta[c] - mean * s;
}

// ---------------- max aggregation (BN affine fused, sign-safe) ---------------------
__global__ void k_maxagg(float* __restrict__ out) {
    int v = blockIdx.x;
    int t = threadIdx.x;
    float4 mx = *reinterpret_cast<const float4*>(g_x + (size_t)v * D + t * 4);
    float4 mn = mx;
    int beg = g_off[v], end = g_off[v + 1];
    int j = beg;
    for (; j + 2 <= end; j += 2) {
        int u0 = g_csr[j], u1 = g_csr[j + 1];
        float4 w0 = *reinterpret_cast<const float4*>(g_x + (size_t)u0 * D + t * 4);
        float4 w1 = *reinterpret_cast<const float4*>(g_x + (size_t)u1 * D + t * 4);
        mx.x = fmaxf(mx.x, fmaxf(w0.x, w1.x)); mn.x = fminf(mn.x, fminf(w0.x, w1.x));
        mx.y = fmaxf(mx.y, fmaxf(w0.y, w1.y)); mn.y = fminf(mn.y, fminf(w0.y, w1.y));
        mx.z = fmaxf(mx.z, fmaxf(w0.z, w1.z)); mn.z = fminf(mn.z, fminf(w0.z, w1.z));
        mx.w = fmaxf(mx.w, fmaxf(w0.w, w1.w)); mn.w = fminf(mn.w, fminf(w0.w, w1.w));
    }
    if (j < end) {
        int u = g_csr[j];
        float4 w = *reinterpret_cast<const float4*>(g_x + (size_t)u * D + t * 4);
        mx.x = fmaxf(mx.x, w.x); mn.x = fminf(mn.x, w.x);
        mx.y = fmaxf(mx.y, w.y); mn.y = fminf(mn.y, w.y);
        mx.z = fmaxf(mx.z, w.z); mn.z = fminf(mn.z, w.z);
        mx.w = fmaxf(mx.w, w.w); mn.w = fminf(mn.w, w.w);
    }
    float4 sc = reinterpret_cast<const float4*>(g_scale)[t];
    float4 sh = reinterpret_cast<const float4*>(g_shift)[t];
    float4 r;
    r.x = (sc.x >= 0.f ? mx.x : mn.x) * sc.x + sh.x;
    r.y = (sc.y >= 0.f ? mx.y : mn.y) * sc.y + sh.y;
    r.z = (sc.z >= 0.f ? mx.z : mn.z) * sc.z + sh.z;
    r.w = (sc.w >= 0.f ? mx.w : mn.w) * sc.w + sh.w;
    reinterpret_cast<float4*>(out + (size_t)v * D)[t] = r;
}

// ---------------- launch -------------------------------------------------------------
extern "C" void kernel_launch(void* const* d_in, const int* in_sizes, int n_in,
                              void* d_out, int out_size) {
    const float* feats = (const float*)d_in[0];
    const int*   src   = (const int*)d_in[1];
    const int*   dst   = (const int*)d_in[2];
    const float* Wl    = (const float*)d_in[3];
    const float* Wr    = (const float*)d_in[4];
    const float* bl    = (const float*)d_in[5];
    const float* gamma = (const float*)d_in[6];
    const float* beta  = (const float*)d_in[7];
    float* out = (float*)d_out;

    int n = in_sizes[0] / D;
    int e = in_sizes[1];

    cudaFuncSetAttribute(k_gemm, cudaFuncAttributeMaxDynamicSharedMemorySize,
                         SMEM_BYTES);

    k_zero<<<(n + 255) / 256, 256>>>(n);
    k_degcount<<<(e + 255) / 256, 256>>>(dst, e);
    k_scan<<<1, 1024>>>(n);
    k_fill<<<(e + n + 255) / 256, 256>>>(src, dst, e, n);
    k_nbrsum<<<n, 128>>>(feats);
    k_gemm<<<dim3(D / TN, MAXT), 256, SMEM_BYTES>>>(feats, Wl, Wr, bl);
    k_finalize<<<1, D>>>(n, gamma, beta);
    k_maxagg<<<n, 128>>>(out);
}

// round 5
// speedup vs baseline: 1.3767x; 1.1371x over previous
#include <cuda_runtime.h>
#include <cstdint>

#define NMAX   20000
#define EMAX   160000
#define D      512
#define NBUK   11
#define TM     128
#define MAXT   ((NMAX + TM - 1) / TM + NBUK)   // 168
#define BN_EPS 1e-5f

#define TN  128
#define TK  32
#define APITCH 36    // words; 144B rows, 16B-aligned, conflict-free frag reads
#define BPITCH 136   // words; 544B rows, 16B-aligned, conflict-free frag reads
#define A_WORDS (TM * APITCH)            // 4608
#define B_WORDS (TK * BPITCH)            // 4352
#define STAGES 3
#define STAGE_WORDS (A_WORDS + B_WORDS)  // 8960 words = 35840 B (16B-aligned)
#define SMEM_WORDS (STAGES * STAGE_WORDS)
#define SMEM_BYTES (SMEM_WORDS*4 + TM*4) // buffers + perm_s = 108032 B

// ---------------- scratch (device globals; no allocation allowed) -------------
__device__ int   g_deg[NMAX];
__device__ int   g_off[NMAX + 1];
__device__ int   g_cur[NMAX];
__device__ int   g_csr[EMAX];
__device__ int   g_bcnt[NBUK];
__device__ int   g_boff[NBUK + 1];
__device__ int   g_bcur[NBUK];
__device__ int   g_perm[NMAX];
__device__ int   g_tile_bucket[MAXT];
__device__ int   g_tile_row[MAXT];
__device__ int   g_tile_rows[MAXT];
__device__ int   g_ntiles;
__device__ float g_h[(size_t)NMAX * D];     // neighbor sums
__device__ float g_x[(size_t)NMAX * D];     // pre-BN linear output
__device__ float g_sum[D], g_sumsq[D], g_scale[D], g_shift[D];

// ---------------- helpers -----------------------------------------------------
__device__ __forceinline__ void mma_tf32(float c[4], const uint32_t a[4],
                                         const uint32_t b[2]) {
    asm volatile(
        "mma.sync.aligned.m16n8k8.row.col.f32.tf32.tf32.f32 "
        "{%0,%1,%2,%3}, {%4,%5,%6,%7}, {%8,%9}, {%0,%1,%2,%3};\n"
        : "+f"(c[0]), "+f"(c[1]), "+f"(c[2]), "+f"(c[3])
        : "r"(a[0]), "r"(a[1]), "r"(a[2]), "r"(a[3]), "r"(b[0]), "r"(b[1]));
}

__device__ __forceinline__ void cp_async16(uint32_t saddr, const void* gaddr,
                                           int src_bytes) {
    asm volatile("cp.async.cg.shared.global [%0], [%1], 16, %2;\n"
                 :: "r"(saddr), "l"(gaddr), "r"(src_bytes));
}
__device__ __forceinline__ void cp_commit() {
    asm volatile("cp.async.commit_group;\n");
}
__device__ __forceinline__ void cp_wait1() {
    asm volatile("cp.async.wait_group 1;\n");
}

// ---------------- setup kernels ------------------------------------------------
__global__ void k_zero(int n) {
    int i = blockIdx.x * blockDim.x + threadIdx.x;
    if (i < n) g_deg[i] = 0;
    if (i < D) { g_sum[i] = 0.f; g_sumsq[i] = 0.f; }
    if (i < NBUK) { g_bcnt[i] = 0; g_bcur[i] = 0; }
}

__global__ void k_degcount(const int* __restrict__ dst, int e) {
    int i = blockIdx.x * blockDim.x + threadIdx.x;
    if (i < e) atomicAdd(&g_deg[dst[i]], 1);
}

// scan (warp-shuffle based) + bucket histogram + tile map, one block
__global__ void k_scan(int n) {
    __shared__ int wsum[32];
    __shared__ int bc[NBUK];
    int t = threadIdx.x, lane = t & 31, w = t >> 5;
    if (t < NBUK) bc[t] = 0;
    int carry = 0;
    int nchunk = (n + 1023) >> 10;
    for (int ch = 0; ch < nchunk; ch++) {
        int i = ch * 1024 + t;
        int v = (i < n) ? g_deg[i] : 0;
        int x = v;
#pragma unroll
        for (int o = 1; o < 32; o <<= 1) {
            int y = __shfl_up_sync(0xffffffffu, x, o);
            if (lane >= o) x += y;
        }
        if (lane == 31) wsum[w] = x;
        __syncthreads();
        if (w == 0) {
            int s = wsum[lane];
#pragma unroll
            for (int o = 1; o < 32; o <<= 1) {
                int y = __shfl_up_sync(0xffffffffu, s, o);
                if (lane >= o) s += y;
            }
            wsum[lane] = s;
        }
        __syncthreads();
        int prev = (w > 0) ? wsum[w - 1] : 0;
        if (i < n) {
            int ex = carry + prev + x - v;
            g_off[i] = ex;
            g_cur[i] = ex;
        }
        carry += wsum[31];
        __syncthreads();
    }
    if (t == 0) g_off[n] = carry;
    for (int i = t; i < n; i += 1024) {
        int dd = g_deg[i];
        if (dd > NBUK - 1) dd = NBUK - 1;
        atomicAdd(&bc[dd], 1);
    }
    __syncthreads();
    if (t == 0) {
        int acc = 0;
        for (int dd = 0; dd < NBUK; dd++) {
            g_bcnt[dd] = bc[dd];
            g_boff[dd] = acc;
            acc += bc[dd];
        }
        g_boff[NBUK] = acc;
        int tt = 0;
        for (int dd = 0; dd < NBUK; dd++) {
            int c = bc[dd], o = g_boff[dd];
            for (int r = 0; r < c; r += TM) {
                g_tile_bucket[tt] = dd;
                g_tile_row[tt]    = o + r;
                g_tile_rows[tt]   = (c - r < TM) ? (c - r) : TM;
                tt++;
            }
        }
        g_ntiles = tt;
    }
}

// CSR fill + bucket fill (merged)
__global__ void k_fill(const int* __restrict__ src, const int* __restrict__ dst,
                       int e, int n) {
    int i = blockIdx.x * blockDim.x + threadIdx.x;
    if (i < e) {
        int pos = atomicAdd(&g_cur[dst[i]], 1);
        g_csr[pos] = src[i];
    }
    int v = i - e;
    if (v >= 0 && v < n) {
        int dd = g_deg[v];
        if (dd > NBUK - 1) dd = NBUK - 1;
        int pos = g_boff[dd] + atomicAdd(&g_bcur[dd], 1);
        g_perm[pos] = v;
    }
}

// ---------------- neighbor sum ---------------------------------------------------
__global__ void k_nbrsum(const float* __restrict__ feats) {
    int v = blockIdx.x;
    int t = threadIdx.x;
    float4 acc = make_float4(0.f, 0.f, 0.f, 0.f);
    int beg = g_off[v], end = g_off[v + 1];
    int j = beg;
    for (; j + 2 <= end; j += 2) {
        int u0 = g_csr[j], u1 = g_csr[j + 1];
        float4 w0 = *reinterpret_cast<const float4*>(feats + (size_t)u0 * D + t * 4);
        float4 w1 = *reinterpret_cast<const float4*>(feats + (size_t)u1 * D + t * 4);
        acc.x += w0.x + w1.x; acc.y += w0.y + w1.y;
        acc.z += w0.z + w1.z; acc.w += w0.w + w1.w;
    }
    if (j < end) {
        int u = g_csr[j];
        float4 w = *reinterpret_cast<const float4*>(feats + (size_t)u * D + t * 4);
        acc.x += w.x; acc.y += w.y; acc.z += w.z; acc.w += w.w;
    }
    *reinterpret_cast<float4*>(g_h + (size_t)v * D + t * 4) = acc;
}

// ---------------- bucketed tf32 GEMM, 3-stage cp.async, occ 2 --------------------
// x[node] = [h|feats](K=1024) @ [Wl[d];Wr[d]](1024x512) + bl[d]; BN stats fused.
__global__ __launch_bounds__(256, 2)
void k_gemm(const float* __restrict__ feats, const float* __restrict__ Wl,
            const float* __restrict__ Wr, const float* __restrict__ bl) {
    int tileId = blockIdx.y;
    if (tileId >= g_ntiles) return;
    int d     = g_tile_bucket[tileId];
    int row0  = g_tile_row[tileId];
    int nrows = g_tile_rows[tileId];
    int n0    = blockIdx.x * TN;

    extern __shared__ float smem[];
    int* perm_s = (int*)(smem + SMEM_WORDS);

    int tid  = threadIdx.x;
    int lane = tid & 31;
    int warp = tid >> 5;
    int grp  = lane >> 2;
    int tig  = lane & 3;
    int wrow0 = (warp & 1) * 64;
    int wcol0 = (warp >> 1) * 32;

    if (tid < TM) perm_s[tid] = (tid < nrows) ? g_perm[row0 + tid] : -1;
    __syncthreads();

    // per-thread load coordinates
    int a_row = tid >> 3, a_f4 = tid & 7;     // + p*32 rows
    int b_kr  = tid >> 5, b_f4 = tid & 31;    // + p*8 k-rows

    uint32_t a_s[4], b_s[4];
    size_t a_goff[4];                          // ELEMENT offsets into g_h/feats
    int a_valid[4];
#pragma unroll
    for (int p = 0; p < 4; p++) {
        int row = a_row + p * 32;
        int node = perm_s[row];
        a_valid[p] = (node >= 0) ? 16 : 0;
        if (node < 0) node = 0;
        a_goff[p] = (size_t)node * D + (size_t)(a_f4 * 4);
        a_s[p] = (uint32_t)__cvta_generic_to_shared(
            &smem[row * APITCH + a_f4 * 4]);
        b_s[p] = (uint32_t)__cvta_generic_to_shared(
            &smem[A_WORDS + (b_kr + p * 8) * BPITCH + b_f4 * 4]);
    }
    const size_t wbase = (size_t)d * D * D + (size_t)n0;

    auto load_stage = [&](int kk, int stg) {
        const float* aptr = (kk < 512) ? g_h : feats;
        const float* wptr = (kk < 512) ? Wl : Wr;
        int kb = kk & 511;
        uint32_t soff = (uint32_t)(stg * (STAGE_WORDS * 4));
#pragma unroll
        for (int p = 0; p < 4; p++)
            cp_async16(a_s[p] + soff, aptr + a_goff[p] + kb, a_valid[p]);
#pragma unroll
        for (int p = 0; p < 4; p++)
            cp_async16(b_s[p] + soff,
                       wptr + wbase + (size_t)(kb + b_kr + p * 8) * D + b_f4 * 4, 16);
    };

    float acc[4][4][4];
#pragma unroll
    for (int mi = 0; mi < 4; mi++)
#pragma unroll
        for (int ni = 0; ni < 4; ni++)
#pragma unroll
            for (int q = 0; q < 4; q++) acc[mi][ni][q] = 0.f;

    load_stage(0, 0); cp_commit();
    load_stage(TK, 1); cp_commit();

    int stage = 0;
#pragma unroll 1
    for (int kt = 0; kt < 1024 / TK; kt++) {
        cp_wait1();
        __syncthreads();
        // prefetch stage kt+2 into the buffer last read at iteration kt-1
        if (kt + 2 < 1024 / TK) {
            int nstg = stage + 2; if (nstg >= STAGES) nstg -= STAGES;
            load_stage((kt + 2) * TK, nstg);
        }
        cp_commit();

        const uint32_t* As = (const uint32_t*)(smem + stage * STAGE_WORDS);
        const uint32_t* Bs = As + A_WORDS;
#pragma unroll
        for (int k8 = 0; k8 < TK; k8 += 8) {
            uint32_t af[4][4], bf[4][2];
#pragma unroll
            for (int mi = 0; mi < 4; mi++) {
                int r0 = wrow0 + mi * 16 + grp;
                af[mi][0] = As[r0 * APITCH + k8 + tig];
                af[mi][1] = As[(r0 + 8) * APITCH + k8 + tig];
                af[mi][2] = As[r0 * APITCH + k8 + tig + 4];
                af[mi][3] = As[(r0 + 8) * APITCH + k8 + tig + 4];
            }
#pragma unroll
            for (int ni = 0; ni < 4; ni++) {
                int c0 = wcol0 + ni * 8 + grp;
                bf[ni][0] = Bs[(k8 + tig) * BPITCH + c0];
                bf[ni][1] = Bs[(k8 + tig + 4) * BPITCH + c0];
            }
#pragma unroll
            for (int mi = 0; mi < 4; mi++)
#pragma unroll
                for (int ni = 0; ni < 4; ni++)
                    mma_tf32(acc[mi][ni], af[mi], bf[ni]);
        }
        stage = stage + 1; if (stage >= STAGES) stage = 0;
    }

    // epilogue: bias add, store, fused BN column sums
    float2 bias[4];
#pragma unroll
    for (int ni = 0; ni < 4; ni++)
        bias[ni] = *reinterpret_cast<const float2*>(
            bl + (size_t)d * D + n0 + wcol0 + ni * 8 + 2 * tig);

    float s_sum[4][2] = {}, s_sq[4][2] = {};
#pragma unroll
    for (int mi = 0; mi < 4; mi++) {
        int r0 = wrow0 + mi * 16 + grp;
        int node0 = perm_s[r0];
        int node1 = perm_s[r0 + 8];
#pragma unroll
        for (int ni = 0; ni < 4; ni++) {
            int cc = wcol0 + ni * 8 + 2 * tig;
            float v0x = acc[mi][ni][0] + bias[ni].x;
            float v0y = acc[mi][ni][1] + bias[ni].y;
            float v1x = acc[mi][ni][2] + bias[ni].x;
            float v1y = acc[mi][ni][3] + bias[ni].y;
            if (node0 >= 0) {
                float2 v; v.x = v0x; v.y = v0y;
                *reinterpret_cast<float2*>(g_x + (size_t)node0 * D + n0 + cc) = v;
                s_sum[ni][0] += v0x; s_sq[ni][0] += v0x * v0x;
                s_sum[ni][1] += v0y; s_sq[ni][1] += v0y * v0y;
            }
            if (node1 >= 0) {
                float2 v; v.x = v1x; v.y = v1y;
                *reinterpret_cast<float2*>(g_x + (size_t)node1 * D + n0 + cc) = v;
                s_sum[ni][0] += v1x; s_sq[ni][0] += v1x * v1x;
                s_sum[ni][1] += v1y; s_sq[ni][1] += v1y * v1y;
            }
        }
    }
    // reduce across the 8 lane-groups (lanes differing in bits 2..4)
#pragma unroll
    for (int ni = 0; ni < 4; ni++)
#pragma unroll
        for (int b = 0; b < 2; b++) {
            float s = s_sum[ni][b], q = s_sq[ni][b];
#pragma unroll
            for (int off = 4; off < 32; off <<= 1) {
                s += __shfl_xor_sync(0xffffffffu, s, off);
                q += __shfl_xor_sync(0xffffffffu, q, off);
            }
            if (grp == 0) {
                int c = n0 + wcol0 + ni * 8 + 2 * tig + b;
                atomicAdd(&g_sum[c], s);
                atomicAdd(&g_sumsq[c], q);
            }
        }
}

// ---------------- BN finalize -----------------------------------------------------
__global__ void k_finalize(int n, const float* __restrict__ gamma,
                           const float* __restrict__ beta) {
    int c = threadIdx.x;
    float invn = 1.f / (float)n;
    float mean = g_sum[c] * invn;
    float var  = g_sumsq[c] * invn - mean * mean;
    float s    = gamma[c] * rsqrtf(var + BN_EPS);
    g_scale[c] = s;
    g_shift[c] = beta[c] - mean * s;
}

// ---------------- max aggregation (BN affine fused, sign-safe) ---------------------
__global__ void k_maxagg(float* __restrict__ out) {
    int v = blockIdx.x;
    int t = threadIdx.x;
    float4 mx = *reinterpret_cast<const float4*>(g_x + (size_t)v * D + t * 4);
    float4 mn = mx;
    int beg = g_off[v], end = g_off[v + 1];
    int j = beg;
    for (; j + 2 <= end; j += 2) {
        int u0 = g_csr[j], u1 = g_csr[j + 1];
        float4 w0 = *reinterpret_cast<const float4*>(g_x + (size_t)u0 * D + t * 4);
        float4 w1 = *reinterpret_cast<const float4*>(g_x + (size_t)u1 * D + t * 4);
        mx.x = fmaxf(mx.x, fmaxf(w0.x, w1.x)); mn.x = fminf(mn.x, fminf(w0.x, w1.x));
        mx.y = fmaxf(mx.y, fmaxf(w0.y, w1.y)); mn.y = fminf(mn.y, fminf(w0.y, w1.y));
        mx.z = fmaxf(mx.z, fmaxf(w0.z, w1.z)); mn.z = fminf(mn.z, fminf(w0.z, w1.z));
        mx.w = fmaxf(mx.w, fmaxf(w0.w, w1.w)); mn.w = fminf(mn.w, fminf(w0.w, w1.w));
    }
    if (j < end) {
        int u = g_csr[j];
        float4 w = *reinterpret_cast<const float4*>(g_x + (size_t)u * D + t * 4);
        mx.x = fmaxf(mx.x, w.x); mn.x = fminf(mn.x, w.x);
        mx.y = fmaxf(mx.y, w.y); mn.y = fminf(mn.y, w.y);
        mx.z = fmaxf(mx.z, w.z); mn.z = fminf(mn.z, w.z);
        mx.w = fmaxf(mx.w, w.w); mn.w = fminf(mn.w, w.w);
    }
    float4 sc = reinterpret_cast<const float4*>(g_scale)[t];
    float4 sh = reinterpret_cast<const float4*>(g_shift)[t];
    float4 r;
    r.x = (sc.x >= 0.f ? mx.x : mn.x) * sc.x + sh.x;
    r.y = (sc.y >= 0.f ? mx.y : mn.y) * sc.y + sh.y;
    r.z = (sc.z >= 0.f ? mx.z : mn.z) * sc.z + sh.z;
    r.w = (sc.w >= 0.f ? mx.w : mn.w) * sc.w + sh.w;
    reinterpret_cast<float4*>(out + (size_t)v * D)[t] = r;
}

// ---------------- launch -------------------------------------------------------------
extern "C" void kernel_launch(void* const* d_in, const int* in_sizes, int n_in,
                              void* d_out, int out_size) {
    const float* feats = (const float*)d_in[0];
    const int*   src   = (const int*)d_in[1];
    const int*   dst   = (const int*)d_in[2];
    const float* Wl    = (const float*)d_in[3];
    const float* Wr    = (const float*)d_in[4];
    const float* bl    = (const float*)d_in[5];
    const float* gamma = (const float*)d_in[6];
    const float* beta  = (const float*)d_in[7];
    float* out = (float*)d_out;

    int n = in_sizes[0] / D;
    int e = in_sizes[1];

    cudaFuncSetAttribute(k_gemm, cudaFuncAttributeMaxDynamicSharedMemorySize,
                         SMEM_BYTES);

    k_zero<<<(n + 255) / 256, 256>>>(n);
    k_degcount<<<(e + 255) / 256, 256>>>(dst, e);
    k_scan<<<1, 1024>>>(n);
    k_fill<<<(e + n + 255) / 256, 256>>>(src, dst, e, n);
    k_nbrsum<<<n, 128>>>(feats);
    k_gemm<<<dim3(D / TN, MAXT), 256, SMEM_BYTES>>>(feats, Wl, Wr, bl);
    k_finalize<<<1, D>>>(n, gamma, beta);
    k_maxagg<<<n, 128>>>(out);
}